// round 16
// baseline (speedup 1.0000x reference)
#include <cuda_runtime.h>

// Problem constants
#define NB 64
#define NF 3000          // frames
#define NF2 1500         // frame pairs
#define NF8 375          // frame octs (4 pairs)
#define NU  125          // 24-frame units (3 octs = 12 pairs each)
#define NFS 80           // frame shift
#define NL 240000        // NF * NFS
#define NP 15            // order-1
#define EMPH 0.97f

// ---------------- scratch (device globals) ----------------------------------
__device__ float g_C1[(size_t)NB * NF2 * 256];   // pair matrices
__device__ float g_V1[(size_t)NB * NF2 * 16];    // pair v
__device__ float g_C3[(size_t)NB * NF8 * 256];   // oct matrices
__device__ float g_V3[(size_t)NB * NF8 * 16];    // oct v
__device__ float g_C4[(size_t)NB * NU  * 256];   // unit matrices
__device__ float g_V4[(size_t)NB * NU  * 16];    // unit v
__device__ float g_S4[(size_t)NB * NU  * 16];    // state+z entering unit
__device__ float g_S1[(size_t)NB * NF2 * 16];    // state+z entering pair

__device__ __forceinline__ float q_pow80()
{
    float q = 1.f;
    #pragma unroll
    for (int t = 0; t < NFS; t++) q *= EMPH;
    return q;
}

// 4-way-split AR step: acc = e - sum_{k=1..15} a[k]*hist[k-1]
__device__ __forceinline__ float ar_step(const float (&a)[16],
                                         const float (&hist)[NP], float e)
{
    float t1 = fmaf(a[2], hist[1], fmaf(a[5], hist[4],
               fmaf(a[8], hist[7], fmaf(a[11], hist[10], a[14] * hist[13]))));
    float t2 = fmaf(a[3], hist[2], fmaf(a[6], hist[5],
               fmaf(a[9], hist[8], fmaf(a[12], hist[11], a[15] * hist[14]))));
    float t3 = fmaf(a[4], hist[3], fmaf(a[7], hist[6],
               fmaf(a[10], hist[9], a[13] * hist[12])));
    return fmaf(-a[1], hist[0], e - ((t1 + t2) + t3));
}

// ---------------- kA: fused per-frame setup + pair compose ------------------
// Phase 1 runs the excitation AR and the impulse AR INTERLEAVED (independent
// chains -> 2x ILP). Rows 0..14 of each augmented matrix in smem.
#define MST 244   // 15 rows x 16 + 4 pad (244 mod 32 = 20 -> 4-way max)

__global__ void __launch_bounds__(32) kA_fused(const float* __restrict__ excit,
                                               const float* __restrict__ lpc)
{
    __shared__ __align__(16) float sA[32 * MST];

    const int lane = threadIdx.x;
    const int idx  = blockIdx.x * 32 + lane;   // global frame (b*NF + f)
    const int b    = idx / NF;
    const int f    = idx - b * NF;

    float v[16];   // this frame's deemph row

    // ======== phase 1 ========
    {
        float a[16];
        const float* ap = lpc + (size_t)idx * 16;
        #pragma unroll
        for (int k = 1; k < 16; k++) a[k] = ap[k];

        float hist[NP], w[NP];
        #pragma unroll
        for (int k = 0; k < NP; k++) { hist[k] = 0.f; w[k] = 0.f; }
        w[0] = 1.f;                 // h[0]
        float wz = 0.f, wacc = 1.f; // W(0)
        float hr[30], warr[16];

        const float4* ep4 = reinterpret_cast<const float4*>(
            excit + (size_t)b * NL + (size_t)f * NFS);
        #pragma unroll
        for (int m4 = 0; m4 < NFS / 4; m4++) {
            float4 e4 = ep4[m4];
            float ev[4] = {e4.x, e4.y, e4.z, e4.w};
            #pragma unroll
            for (int q = 0; q < 4; q++) {
                const int n = m4 * 4 + q;
                // chain A: excitation
                float acc = ar_step(a, hist, ev[q]);
                // chain B: impulse response h[n] (independent of chain A)
                if (n >= 1) {
                    float hn = ar_step(a, w, 0.f);
                    wacc = fmaf(EMPH, wacc, hn);
                    if (n >= 50) hr[n - 50] = hn;
                    if (n >= 64) warr[n - 64] = wacc;
                    #pragma unroll
                    for (int k = NP - 1; k >= 1; k--) w[k] = w[k - 1];
                    w[0] = hn;
                }
                #pragma unroll
                for (int k = NP - 1; k >= 1; k--) hist[k] = hist[k - 1];
                hist[0] = acc;
                wz = fmaf(EMPH, wz, acc);
            }
        }

        float* Ap = sA + lane * MST;
        float prev[17];
        #pragma unroll
        for (int j = 1; j <= NP; j++) {
            float acc = 0.f;
            #pragma unroll
            for (int t = 0; t <= NP - j; t++)
                acc = fmaf(a[j + t], hr[15 - t], acc);
            prev[j] = -acc;
        }
        {
            float4* o = reinterpret_cast<float4*>(Ap + 14 * 16);
            o[0] = make_float4(prev[1],  prev[2],  prev[3],  prev[4]);
            o[1] = make_float4(prev[5],  prev[6],  prev[7],  prev[8]);
            o[2] = make_float4(prev[9],  prev[10], prev[11], prev[12]);
            o[3] = make_float4(prev[13], prev[14], prev[15], hist[14]);
        }
        #pragma unroll
        for (int i = 14; i >= 1; i--) {
            float hv = hr[30 - i];
            float cur[16];
            #pragma unroll
            for (int j = 1; j <= 14; j++) cur[j] = fmaf(-a[j], hv, prev[j + 1]);
            cur[15] = -a[15] * hv;
            float4* o = reinterpret_cast<float4*>(Ap + (i - 1) * 16);
            o[0] = make_float4(cur[1],  cur[2],  cur[3],  cur[4]);
            o[1] = make_float4(cur[5],  cur[6],  cur[7],  cur[8]);
            o[2] = make_float4(cur[9],  cur[10], cur[11], cur[12]);
            o[3] = make_float4(cur[13], cur[14], cur[15], hist[i - 1]);
            #pragma unroll
            for (int j = 1; j <= 15; j++) prev[j] = cur[j];
        }

        #pragma unroll
        for (int j = 1; j <= NP; j++) {
            float acc = 0.f;
            #pragma unroll
            for (int t = 0; t <= NP - j; t++)
                acc = fmaf(a[j + t], warr[15 - t], acc);
            v[j - 1] = -acc;
        }
        v[15] = wz;
    }
    __syncthreads();

    // pull even lane's v into odd lane (v1)
    float vv1[16];
    #pragma unroll
    for (int q = 0; q < 16; q++)
        vv1[q] = __shfl_up_sync(0xffffffffu, v[q], 1);

    const int p    = lane >> 1;
    const int half = lane & 1;
    const float* A1 = sA + (2 * p)     * MST;
    const float* A2 = sA + (2 * p + 1) * MST;
    const size_t P  = (size_t)blockIdx.x * 16 + p;
    float* Cp = g_C1 + P * 256;
    const float Q = q_pow80();

    // ---- v output FIRST (releases v/vv1 registers before matrix passes) ----
    if (half == 1) {
        float acc[16];
        #pragma unroll
        for (int q = 0; q < 16; q++) acc[q] = Q * vv1[q];
        acc[15] += v[15];              // A1 row 15 = e15 term of v2^T*A1
        #pragma unroll
        for (int k = 0; k < 15; k++) {
            const float4* rr = reinterpret_cast<const float4*>(A1 + k * 16);
            float4 y0 = rr[0], y1 = rr[1], y2 = rr[2], y3 = rr[3];
            float a1r[16] = {y0.x,y0.y,y0.z,y0.w, y1.x,y1.y,y1.z,y1.w,
                             y2.x,y2.y,y2.z,y2.w, y3.x,y3.y,y3.z,y3.w};
            float c = v[k];
            #pragma unroll
            for (int q = 0; q < 16; q++) acc[q] = fmaf(c, a1r[q], acc[q]);
        }
        float4* vo = reinterpret_cast<float4*>(g_V1 + P * 16);
        vo[0] = make_float4(acc[0],  acc[1],  acc[2],  acc[3]);
        vo[1] = make_float4(acc[4],  acc[5],  acc[6],  acc[7]);
        vo[2] = make_float4(acc[8],  acc[9],  acc[10], acc[11]);
        vo[3] = make_float4(acc[12], acc[13], acc[14], acc[15]);
    }

    // ---- matrix passes (augmented: skip k=15, row15=e15) ----
    #pragma unroll
    for (int pass = 0; pass < 2; pass++) {
        int rbase = half * 8 + pass * 4;
        float a2r[4][16];
        #pragma unroll
        for (int j = 0; j < 4; j++) {
            int r = rbase + j;
            if (r < 15) {
                const float4* rr = reinterpret_cast<const float4*>(A2 + r * 16);
                float4 x0 = rr[0], x1 = rr[1], x2 = rr[2], x3 = rr[3];
                a2r[j][0]=x0.x;  a2r[j][1]=x0.y;  a2r[j][2]=x0.z;  a2r[j][3]=x0.w;
                a2r[j][4]=x1.x;  a2r[j][5]=x1.y;  a2r[j][6]=x1.z;  a2r[j][7]=x1.w;
                a2r[j][8]=x2.x;  a2r[j][9]=x2.y;  a2r[j][10]=x2.z; a2r[j][11]=x2.w;
                a2r[j][12]=x3.x; a2r[j][13]=x3.y; a2r[j][14]=x3.z; a2r[j][15]=x3.w;
            } else {
                #pragma unroll
                for (int q = 0; q < 16; q++) a2r[j][q] = (q == 15) ? 1.f : 0.f;
            }
        }
        float acc[4][16];
        #pragma unroll
        for (int j = 0; j < 4; j++) {
            #pragma unroll
            for (int q = 0; q < 15; q++) acc[j][q] = 0.f;
            acc[j][15] = a2r[j][15];   // M1 row 15 = e15 -> b2 contribution
        }

        #pragma unroll
        for (int k = 0; k < 15; k++) {
            const float4* rr = reinterpret_cast<const float4*>(A1 + k * 16);
            float4 y0 = rr[0], y1 = rr[1], y2 = rr[2], y3 = rr[3];
            float a1r[16] = {y0.x,y0.y,y0.z,y0.w, y1.x,y1.y,y1.z,y1.w,
                             y2.x,y2.y,y2.z,y2.w, y3.x,y3.y,y3.z,y3.w};
            #pragma unroll
            for (int j = 0; j < 4; j++) {
                float c = a2r[j][k];
                #pragma unroll
                for (int q = 0; q < 16; q++)
                    acc[j][q] = fmaf(c, a1r[q], acc[j][q]);
            }
        }
        #pragma unroll
        for (int j = 0; j < 4; j++) {
            float4* o = reinterpret_cast<float4*>(Cp + (rbase + j) * 16);
            o[0] = make_float4(acc[j][0],  acc[j][1],  acc[j][2],  acc[j][3]);
            o[1] = make_float4(acc[j][4],  acc[j][5],  acc[j][6],  acc[j][7]);
            o[2] = make_float4(acc[j][8],  acc[j][9],  acc[j][10], acc[j][11]);
            o[3] = make_float4(acc[j][12], acc[j][13], acc[j][14], acc[j][15]);
        }
    }
}

// ---------------- compose_oct: radix-4 C1 -> C3 (2 octs per warp) -----------
__global__ void __launch_bounds__(256) k_compose_oct()
{
    __shared__ float sM[16][272];
    __shared__ float sv[16][16];

    const int wig  = threadIdx.x >> 5;
    const int lane = threadIdx.x & 31;
    const int hl   = lane >> 4;
    const int i    = lane & 15;
    const int slot = wig * 2 + hl;
    const int gw   = blockIdx.x * 16 + slot;    // global oct index
    const int b    = gw / NF8;
    const int o    = gw - b * NF8;

    float q1 = q_pow80();
    const float Qp = q1 * q1;

    size_t e = (size_t)b * NF2 + 4 * o;
    const float* C = g_C1 + e * 256;
    const float* V = g_V1 + e * 16;

    {
        const float4* rr = reinterpret_cast<const float4*>(C + i * 16);
        float4 x0 = rr[0], x1 = rr[1], x2 = rr[2], x3 = rr[3];
        float* d = &sM[slot][i * 17];
        d[0]=x0.x;  d[1]=x0.y;  d[2]=x0.z;  d[3]=x0.w;
        d[4]=x1.x;  d[5]=x1.y;  d[6]=x1.z;  d[7]=x1.w;
        d[8]=x2.x;  d[9]=x2.y;  d[10]=x2.z; d[11]=x2.w;
        d[12]=x3.x; d[13]=x3.y; d[14]=x3.z; d[15]=x3.w;
    }
    float vcur = V[i];
    __syncwarp();

    float mrow[16];
    #pragma unroll
    for (int s = 1; s <= 3; s++) {
        sv[slot][i] = V[s * 16 + i];
        __syncwarp();

        const float4* nr = reinterpret_cast<const float4*>(C + s * 256 + i * 16);
        float4 n0 = nr[0], n1 = nr[1], n2 = nr[2], n3 = nr[3];
        float nc[16] = {n0.x,n0.y,n0.z,n0.w, n1.x,n1.y,n1.z,n1.w,
                        n2.x,n2.y,n2.z,n2.w, n3.x,n3.y,n3.z,n3.w};
        #pragma unroll
        for (int q = 0; q < 16; q++) mrow[q] = 0.f;
        #pragma unroll
        for (int k = 0; k < 15; k++) {           // k=15: Mcur row = e15
            float c = nc[k];
            const float* mk = &sM[slot][k * 17];
            #pragma unroll
            for (int q = 0; q < 16; q++) mrow[q] = fmaf(c, mk[q], mrow[q]);
        }
        mrow[15] += nc[15];                       // e15 contribution

        float accv = 0.f;
        #pragma unroll
        for (int k = 0; k < 15; k++)
            accv = fmaf(sM[slot][k * 17 + i], sv[slot][k], accv);
        if (i == 15) accv += sv[slot][15];        // column 15 of e15 row
        vcur = fmaf(Qp, vcur, accv);

        __syncwarp();
        if (s < 3) {
            float* d = &sM[slot][i * 17];
            #pragma unroll
            for (int q = 0; q < 16; q++) d[q] = mrow[q];
            __syncwarp();
        }
    }

    float4* og = reinterpret_cast<float4*>(g_C3 + (size_t)gw * 256 + i * 16);
    og[0] = make_float4(mrow[0],  mrow[1],  mrow[2],  mrow[3]);
    og[1] = make_float4(mrow[4],  mrow[5],  mrow[6],  mrow[7]);
    og[2] = make_float4(mrow[8],  mrow[9],  mrow[10], mrow[11]);
    og[3] = make_float4(mrow[12], mrow[13], mrow[14], mrow[15]);
    g_V3[(size_t)gw * 16 + i] = vcur;
}

// ---------------- compose4: radix-3 (3 octs -> 1 unit) ----------------------
__global__ void __launch_bounds__(256) k_compose4()
{
    __shared__ float sF[8][272];
    __shared__ float sT[8][272];
    __shared__ float sv2[8][16];

    const int wig  = threadIdx.x >> 5;
    const int lane = threadIdx.x & 31;
    const int gw   = blockIdx.x * 8 + wig;
    const int b    = gw / NU;
    const int u    = gw - b * NU;
    const bool act = lane < 16;
    const int i    = lane;

    float q1 = q_pow80();
    float q2 = q1 * q1, q4 = q2 * q2;
    const float QO = q4 * q4;

    size_t e = (size_t)b * NF8 + 3 * u;
    const float* F  = g_C3 + e * 256;
    const float* S  = F + 256;
    const float* R  = F + 512;
    const float* vF = g_V3 + e * 16;
    const float* vS = vF + 16;
    const float* vR = vF + 32;

    if (act) {
        const float4* frp = reinterpret_cast<const float4*>(F + i * 16);
        float4 f0 = frp[0], f1 = frp[1], f2 = frp[2], f3 = frp[3];
        float* d = &sF[wig][i * 17];
        d[0]=f0.x;  d[1]=f0.y;  d[2]=f0.z;  d[3]=f0.w;
        d[4]=f1.x;  d[5]=f1.y;  d[6]=f1.z;  d[7]=f1.w;
        d[8]=f2.x;  d[9]=f2.y;  d[10]=f2.z; d[11]=f2.w;
        d[12]=f3.x; d[13]=f3.y; d[14]=f3.z; d[15]=f3.w;
        sv2[wig][i] = vS[i];
    }
    __syncwarp();

    float vT_i = 0.f;
    if (act) {
        const float4* srp = reinterpret_cast<const float4*>(S + i * 16);
        float4 s0 = srp[0], s1 = srp[1], s2 = srp[2], s3 = srp[3];
        float sr[16] = {s0.x,s0.y,s0.z,s0.w, s1.x,s1.y,s1.z,s1.w,
                        s2.x,s2.y,s2.z,s2.w, s3.x,s3.y,s3.z,s3.w};
        float trow[16];
        #pragma unroll
        for (int q = 0; q < 16; q++) trow[q] = 0.f;
        #pragma unroll
        for (int k = 0; k < 16; k++) {
            float c = sr[k];
            const float* fk = &sF[wig][k * 17];
            #pragma unroll
            for (int q = 0; q < 16; q++) trow[q] = fmaf(c, fk[q], trow[q]);
        }
        float accv = 0.f;
        #pragma unroll
        for (int k = 0; k < 16; k++)
            accv = fmaf(sF[wig][k * 17 + i], sv2[wig][k], accv);
        vT_i = fmaf(QO, vF[i], accv);
        float* dt = &sT[wig][i * 17];
        #pragma unroll
        for (int q = 0; q < 16; q++) dt[q] = trow[q];
    }
    __syncwarp();
    if (act) sv2[wig][i] = vR[i];
    __syncwarp();

    if (act) {
        const float4* rrp = reinterpret_cast<const float4*>(R + i * 16);
        float4 r0 = rrp[0], r1 = rrp[1], r2 = rrp[2], r3 = rrp[3];
        float rr[16] = {r0.x,r0.y,r0.z,r0.w, r1.x,r1.y,r1.z,r1.w,
                        r2.x,r2.y,r2.z,r2.w, r3.x,r3.y,r3.z,r3.w};
        float mrow[16];
        #pragma unroll
        for (int q = 0; q < 16; q++) mrow[q] = 0.f;
        #pragma unroll
        for (int k = 0; k < 16; k++) {
            float c = rr[k];
            const float* tk = &sT[wig][k * 17];
            #pragma unroll
            for (int q = 0; q < 16; q++) mrow[q] = fmaf(c, tk[q], mrow[q]);
        }
        float accv = 0.f;
        #pragma unroll
        for (int k = 0; k < 16; k++)
            accv = fmaf(sT[wig][k * 17 + i], sv2[wig][k], accv);
        float vM_i = fmaf(QO, vT_i, accv);

        float4* o = reinterpret_cast<float4*>(g_C4 + (size_t)gw * 256 + i * 16);
        o[0] = make_float4(mrow[0],  mrow[1],  mrow[2],  mrow[3]);
        o[1] = make_float4(mrow[4],  mrow[5],  mrow[6],  mrow[7]);
        o[2] = make_float4(mrow[8],  mrow[9],  mrow[10], mrow[11]);
        o[3] = make_float4(mrow[12], mrow[13], mrow[14], mrow[15]);
        g_V4[(size_t)gw * 16 + i] = vM_i;
    }
}

// ---------------- K2: unit-level scan, 25-unit chunks -----------------------
#define CH4 25             // units per chunk
#define NCH4 5             // NU / CH4
#define CU 84              // float4 per unit in smem (16 rows x 5 + 4 v)
#define CG 68              // float4 per unit in global (64 + 4)
#define CHS (CH4 * CU)     // 2100 float4 = 33600 B
#define CHG (CH4 * CG)     // 1700 float4
#define NPF ((CHG + 255) / 256)   // 7 prefetch regs per thread

__device__ __forceinline__ int k2_dst(int i)
{
    int u = i / CG, r = i - u * CG;
    return u * CU + (r < 64 ? (r >> 2) * 5 + (r & 3) : 80 + (r - 64));
}

__global__ void __launch_bounds__(256, 1) k2_scan()
{
    __shared__ float4 sbuf[CHS];
    __shared__ __align__(16) float st[16];

    const int b    = blockIdx.x;
    const int tid  = threadIdx.x;
    const int lane = tid & 31;
    const int wid  = tid >> 5;

    float q1 = q_pow80();
    float q2 = q1 * q1, q4 = q2 * q2;
    const float QO = q4 * q4;
    const float QU = QO * QO * QO;               // 0.97^1920

    const float4* srcm = reinterpret_cast<const float4*>(g_C4) + (size_t)b * NU * 64;
    const float4* srcv = reinterpret_cast<const float4*>(g_V4) + (size_t)b * NU * 4;
    float* Sp = g_S4 + (size_t)b * NU * 16 + lane;

    if (tid < 16) st[tid] = (tid == 15) ? 1.f : 0.f;

    for (int i = tid; i < CHG; i += 256) {
        int u = i / CG, r = i - u * CG;
        float4 vl = (r < 64) ? srcm[(size_t)u * 64 + r]
                             : srcv[(size_t)u * 4 + (r - 64)];
        sbuf[k2_dst(i)] = vl;
    }
    __syncthreads();

    float sv = 0.f;
    int f = 0;
    for (int c = 0; c < NCH4; c++) {
        float4 pre[NPF];
        bool haveNext = (c + 1 < NCH4);
        if (haveNext) {
            int ub = (c + 1) * CH4;
            #pragma unroll
            for (int k = 0; k < NPF; k++) {
                int i = tid + k * 256;
                if (i < CHG) {
                    int u = i / CG, r = i - u * CG;
                    pre[k] = (r < 64) ? srcm[(size_t)(ub + u) * 64 + r]
                                      : srcv[(size_t)(ub + u) * 4 + (r - 64)];
                }
            }
        }

        if (wid == 0) {
            #pragma unroll 5
            for (int d = 0; d < CH4; d++, f++) {
                const float4* rp = (lane < 15) ? (sbuf + d * CU + lane * 5)
                                               : (sbuf + d * CU + 80);
                float4 r0 = rp[0], r1 = rp[1], r2 = rp[2], r3 = rp[3];
                const float4* stv = reinterpret_cast<const float4*>(st);
                float4 s0 = stv[0], s1 = stv[1], s2 = stv[2], s3 = stv[3];

                if (lane < 16) Sp[(size_t)f * 16] = sv;

                float acc0 = fmaf(r0.x, s0.x, fmaf(r0.y, s0.y,
                             fmaf(r0.z, s0.z, r0.w * s0.w)));
                float acc1 = fmaf(r1.x, s1.x, fmaf(r1.y, s1.y,
                             fmaf(r1.z, s1.z, r1.w * s1.w)));
                float acc2 = fmaf(r2.x, s2.x, fmaf(r2.y, s2.y,
                             fmaf(r2.z, s2.z, r2.w * s2.w)));
                float acc3 = fmaf(r3.x, s3.x, fmaf(r3.y, s3.y,
                             fmaf(r3.z, s3.z, r3.w * s3.w)));
                float nsv = (acc0 + acc1) + (acc2 + acc3);
                if (lane == 15) nsv = fmaf(QU, sv, nsv);

                if (lane < NP) st[lane] = nsv;
                __syncwarp(0xffffffffu);
                sv = nsv;
            }
        }
        __syncthreads();

        if (haveNext) {
            #pragma unroll
            for (int k = 0; k < NPF; k++) {
                int i = tid + k * 256;
                if (i < CHG) sbuf[k2_dst(i)] = pre[k];
            }
        }
        __syncthreads();
    }
}

// ---------------- shfl matvec -------------------------------------------------
__device__ __forceinline__ float mv_shfl(const float4& r0, const float4& r1,
                                         const float4& r2, const float4& r3,
                                         float sv)
{
    float acc0 = r3.w;
    float acc1 = 0.f, acc2 = 0.f, acc3 = 0.f;
    float bc;
    bc = __shfl_sync(0xffffffffu, sv,  0); acc0 = fmaf(r0.x, bc, acc0);
    bc = __shfl_sync(0xffffffffu, sv,  1); acc1 = fmaf(r0.y, bc, acc1);
    bc = __shfl_sync(0xffffffffu, sv,  2); acc2 = fmaf(r0.z, bc, acc2);
    bc = __shfl_sync(0xffffffffu, sv,  3); acc3 = fmaf(r0.w, bc, acc3);
    bc = __shfl_sync(0xffffffffu, sv,  4); acc0 = fmaf(r1.x, bc, acc0);
    bc = __shfl_sync(0xffffffffu, sv,  5); acc1 = fmaf(r1.y, bc, acc1);
    bc = __shfl_sync(0xffffffffu, sv,  6); acc2 = fmaf(r1.z, bc, acc2);
    bc = __shfl_sync(0xffffffffu, sv,  7); acc3 = fmaf(r1.w, bc, acc3);
    bc = __shfl_sync(0xffffffffu, sv,  8); acc0 = fmaf(r2.x, bc, acc0);
    bc = __shfl_sync(0xffffffffu, sv,  9); acc1 = fmaf(r2.y, bc, acc1);
    bc = __shfl_sync(0xffffffffu, sv, 10); acc2 = fmaf(r2.z, bc, acc2);
    bc = __shfl_sync(0xffffffffu, sv, 11); acc3 = fmaf(r2.w, bc, acc3);
    bc = __shfl_sync(0xffffffffu, sv, 12); acc0 = fmaf(r3.x, bc, acc0);
    bc = __shfl_sync(0xffffffffu, sv, 13); acc1 = fmaf(r3.y, bc, acc1);
    bc = __shfl_sync(0xffffffffu, sv, 14); acc2 = fmaf(r3.z, bc, acc2);
    return (acc0 + acc1) + (acc2 + acc3);
}

// ---------------- k_fill: unit state -> all 12 pair states (11 matvecs) -----
__global__ void k_fill()
{
    int gw = (blockIdx.x * blockDim.x + threadIdx.x) >> 5;
    int lane = threadIdx.x & 31;
    if (gw >= NB * NU) return;
    int b = gw / NU;
    int u = gw - b * NU;

    float q1 = q_pow80();
    const float Qp = q1 * q1;     // per-pair decay

    float sv = 0.f;
    const float* s4 = g_S4 + (size_t)gw * 16;
    if (lane < 16) sv = s4[lane];

    size_t e = (size_t)b * NF2 + 12 * u;     // first pair of this unit
    float* s1 = g_S1 + e * 16;
    if (lane < 16) s1[lane] = sv;

    #pragma unroll
    for (int s = 0; s < 11; s++) {
        const float4* rp = (lane < 15)
            ? reinterpret_cast<const float4*>(g_C1 + (e + s) * 256) + lane * 4
            : reinterpret_cast<const float4*>(g_V1 + (e + s) * 16);
        float4 r0 = rp[0], r1 = rp[1], r2 = rp[2], r3 = rp[3];
        float sn = mv_shfl(r0, r1, r2, r3, sv);
        if (lane == 15) sn = fmaf(Qp, sv, sn);
        sv = sn;
        if (lane < 16) s1[(s + 1) * 16 + lane] = sv;
    }
}

// ---------------- K3: per-pair replay, smem-staged coalesced I/O -------------
#define K3P 64   // pairs per block

__global__ void __launch_bounds__(K3P, 1) k3_apply(const float* __restrict__ excit,
                                                   const float* __restrict__ lpc,
                                                   float* __restrict__ out)
{
    __shared__ float4 sd[K3P * 41];

    const int tid = threadIdx.x;
    const int P0  = blockIdx.x * K3P;

    for (int e = tid; e < K3P * 40; e += K3P) {
        int j = e / 40, o = e - j * 40;
        int gp = P0 + j;
        int b = gp / NF2, g = gp - b * NF2;
        const float4* src = reinterpret_cast<const float4*>(
            excit + (size_t)b * NL + (size_t)g * 2 * NFS);
        sd[j * 41 + o] = src[o];
    }
    __syncthreads();

    {
        int gp = P0 + tid;
        int b = gp / NF2, g = gp - b * NF2;

        float aA[16], aB[16];
        const float* apA = lpc + ((size_t)b * NF + 2 * g) * 16;
        #pragma unroll
        for (int k = 1; k < 16; k++) aA[k] = apA[k];
        #pragma unroll
        for (int k = 1; k < 16; k++) aB[k] = apA[16 + k];

        const float* sp = g_S1 + (size_t)gp * 16;
        float hist[NP];
        #pragma unroll
        for (int k = 0; k < NP; k++) hist[k] = sp[k];
        float w = sp[15];

        float4* my = &sd[tid * 41];
        #pragma unroll
        for (int m4 = 0; m4 < 40; m4++) {
            float4 e4 = my[m4];
            float ev[4] = {e4.x, e4.y, e4.z, e4.w};
            float ov[4];
            const bool first = (m4 < 20);
            #pragma unroll
            for (int q = 0; q < 4; q++) {
                float acc = first ? ar_step(aA, hist, ev[q])
                                  : ar_step(aB, hist, ev[q]);
                #pragma unroll
                for (int k = NP - 1; k >= 1; k--) hist[k] = hist[k - 1];
                hist[0] = acc;
                w = fmaf(EMPH, w, acc);
                ov[q] = w;
            }
            my[m4] = make_float4(ov[0], ov[1], ov[2], ov[3]);
        }
    }
    __syncthreads();

    for (int e = tid; e < K3P * 40; e += K3P) {
        int j = e / 40, o = e - j * 40;
        int gp = P0 + j;
        int b = gp / NF2, g = gp - b * NF2;
        float4* dst = reinterpret_cast<float4*>(
            out + (size_t)b * NL + (size_t)g * 2 * NFS);
        dst[o] = sd[j * 41 + o];
    }
}

// ---------------- launch -----------------------------------------------------
extern "C" void kernel_launch(void* const* d_in, const int* in_sizes, int n_in,
                              void* d_out, int out_size)
{
    const float* excit = (const float*)d_in[0];
    const float* lpc   = (const float*)d_in[1];
    if (n_in >= 2 && in_sizes[0] == NB * NF * 16 && in_sizes[1] == NB * NL) {
        excit = (const float*)d_in[1];
        lpc   = (const float*)d_in[0];
    }
    float* out = (float*)d_out;

    kA_fused<<<NB * NF / 32, 32>>>(excit, lpc);
    k_compose_oct<<<NB * NF8 / 16, 256>>>();
    k_compose4<<<NB * NU / 8, 256>>>();
    k2_scan<<<NB, 256>>>();                       // 4th launch (profiled)
    k_fill<<<NB * NU * 32 / 256, 256>>>();
    k3_apply<<<NB * NF2 / K3P, K3P>>>(excit, lpc, out);
}

// round 17
// speedup vs baseline: 1.0388x; 1.0388x over previous
#include <cuda_runtime.h>

// Problem constants
#define NB 64
#define NF 3000          // frames
#define NF2 1500         // frame pairs
#define NF8 375          // frame octs (4 pairs)
#define NU  125          // 24-frame units (3 octs = 12 pairs each)
#define NSU 25           // super-units (5 units = 120 frames each)
#define NFS 80           // frame shift
#define NL 240000        // NF * NFS
#define NP 15            // order-1
#define EMPH 0.97f

// ---------------- scratch (device globals) ----------------------------------
__device__ float g_C1[(size_t)NB * NF2 * 256];   // pair matrices
__device__ float g_V1[(size_t)NB * NF2 * 16];    // pair v
__device__ float g_C3[(size_t)NB * NF8 * 256];   // oct matrices
__device__ float g_V3[(size_t)NB * NF8 * 16];    // oct v
__device__ float g_C4[(size_t)NB * NU  * 256];   // unit matrices
__device__ float g_V4[(size_t)NB * NU  * 16];    // unit v
__device__ float g_C5[(size_t)NB * NSU * 256];   // super-unit matrices
__device__ float g_V5[(size_t)NB * NSU * 16];    // super-unit v
__device__ float g_S5[(size_t)NB * NSU * 16];    // state+z entering super-unit
__device__ float g_S4[(size_t)NB * NU  * 16];    // state+z entering unit
__device__ float g_S1[(size_t)NB * NF2 * 16];    // state+z entering pair

__device__ __forceinline__ float q_pow80()
{
    float q = 1.f;
    #pragma unroll
    for (int t = 0; t < NFS; t++) q *= EMPH;
    return q;
}

// 4-way-split AR step: acc = e - sum_{k=1..15} a[k]*hist[k-1]
__device__ __forceinline__ float ar_step(const float (&a)[16],
                                         const float (&hist)[NP], float e)
{
    float t1 = fmaf(a[2], hist[1], fmaf(a[5], hist[4],
               fmaf(a[8], hist[7], fmaf(a[11], hist[10], a[14] * hist[13]))));
    float t2 = fmaf(a[3], hist[2], fmaf(a[6], hist[5],
               fmaf(a[9], hist[8], fmaf(a[12], hist[11], a[15] * hist[14]))));
    float t3 = fmaf(a[4], hist[3], fmaf(a[7], hist[6],
               fmaf(a[10], hist[9], a[13] * hist[12])));
    return fmaf(-a[1], hist[0], e - ((t1 + t2) + t3));
}

// ---------------- kA: fused per-frame setup + pair compose (R14 version) ----
#define MST 276   // padded floats per matrix (276 mod 32 = 20 -> 4-way max)

__global__ void __launch_bounds__(32) kA_fused(const float* __restrict__ excit,
                                               const float* __restrict__ lpc)
{
    __shared__ __align__(16) float sA[32 * MST];
    __shared__ __align__(16) float sV[32 * 16];

    const int lane = threadIdx.x;
    const int idx  = blockIdx.x * 32 + lane;   // global frame (b*NF + f)
    const int b    = idx / NF;
    const int f    = idx - b * NF;

    // ======== phase 1: per-frame matrix + v into smem ========
    {
        float a[16];
        const float* ap = lpc + (size_t)idx * 16;
        #pragma unroll
        for (int k = 1; k < 16; k++) a[k] = ap[k];

        float hist[NP];
        #pragma unroll
        for (int k = 0; k < NP; k++) hist[k] = 0.f;
        float wz = 0.f;
        const float4* ep4 = reinterpret_cast<const float4*>(
            excit + (size_t)b * NL + (size_t)f * NFS);
        #pragma unroll
        for (int m4 = 0; m4 < NFS / 4; m4++) {
            float4 e4 = ep4[m4];
            float ev[4] = {e4.x, e4.y, e4.z, e4.w};
            #pragma unroll
            for (int q = 0; q < 4; q++) {
                float acc = ar_step(a, hist, ev[q]);
                #pragma unroll
                for (int k = NP - 1; k >= 1; k--) hist[k] = hist[k - 1];
                hist[0] = acc;
                wz = fmaf(EMPH, wz, acc);
            }
        }

        float w[NP];
        #pragma unroll
        for (int k = 0; k < NP; k++) w[k] = 0.f;
        w[0] = 1.f;
        float wacc = 1.f;
        float hr[30];
        float warr[16];
        #pragma unroll
        for (int n = 1; n < NFS; n++) {
            float hn = ar_step(a, w, 0.f);
            wacc = fmaf(EMPH, wacc, hn);
            if (n >= 50) hr[n - 50] = hn;
            if (n >= 64) warr[n - 64] = wacc;
            #pragma unroll
            for (int k = NP - 1; k >= 1; k--) w[k] = w[k - 1];
            w[0] = hn;
        }

        float* Ap = sA + lane * MST;
        float prev[17];
        #pragma unroll
        for (int j = 1; j <= NP; j++) {
            float acc = 0.f;
            #pragma unroll
            for (int t = 0; t <= NP - j; t++)
                acc = fmaf(a[j + t], hr[15 - t], acc);
            prev[j] = -acc;
        }
        {
            float4* o = reinterpret_cast<float4*>(Ap + 14 * 16);
            o[0] = make_float4(prev[1],  prev[2],  prev[3],  prev[4]);
            o[1] = make_float4(prev[5],  prev[6],  prev[7],  prev[8]);
            o[2] = make_float4(prev[9],  prev[10], prev[11], prev[12]);
            o[3] = make_float4(prev[13], prev[14], prev[15], hist[14]);
        }
        #pragma unroll
        for (int i = 14; i >= 1; i--) {
            float hv = hr[30 - i];
            float cur[16];
            #pragma unroll
            for (int j = 1; j <= 14; j++) cur[j] = fmaf(-a[j], hv, prev[j + 1]);
            cur[15] = -a[15] * hv;
            float4* o = reinterpret_cast<float4*>(Ap + (i - 1) * 16);
            o[0] = make_float4(cur[1],  cur[2],  cur[3],  cur[4]);
            o[1] = make_float4(cur[5],  cur[6],  cur[7],  cur[8]);
            o[2] = make_float4(cur[9],  cur[10], cur[11], cur[12]);
            o[3] = make_float4(cur[13], cur[14], cur[15], hist[i - 1]);
            #pragma unroll
            for (int j = 1; j <= 15; j++) prev[j] = cur[j];
        }
        {
            float4* o = reinterpret_cast<float4*>(Ap + 15 * 16);
            o[0] = make_float4(0.f, 0.f, 0.f, 0.f);
            o[1] = make_float4(0.f, 0.f, 0.f, 0.f);
            o[2] = make_float4(0.f, 0.f, 0.f, 0.f);
            o[3] = make_float4(0.f, 0.f, 0.f, 1.f);
        }

        float v[16];
        #pragma unroll
        for (int j = 1; j <= NP; j++) {
            float acc = 0.f;
            #pragma unroll
            for (int t = 0; t <= NP - j; t++)
                acc = fmaf(a[j + t], warr[15 - t], acc);
            v[j - 1] = -acc;
        }
        v[15] = wz;
        float4* vo = reinterpret_cast<float4*>(sV + lane * 16);
        vo[0] = make_float4(v[0],  v[1],  v[2],  v[3]);
        vo[1] = make_float4(v[4],  v[5],  v[6],  v[7]);
        vo[2] = make_float4(v[8],  v[9],  v[10], v[11]);
        vo[3] = make_float4(v[12], v[13], v[14], v[15]);
    }
    __syncthreads();

    // ======== phase 2: pair product (augmented structure: skip k=15) ========
    const int p    = lane >> 1;
    const int half = lane & 1;
    const float* A1 = sA + (2 * p)     * MST;
    const float* A2 = sA + (2 * p + 1) * MST;
    const size_t P  = (size_t)blockIdx.x * 16 + p;
    float* Cp = g_C1 + P * 256;
    const float Q = q_pow80();

    #pragma unroll
    for (int pass = 0; pass < 2; pass++) {
        int rbase = half * 8 + pass * 4;
        float a2r[4][16];
        #pragma unroll
        for (int j = 0; j < 4; j++) {
            const float4* rr = reinterpret_cast<const float4*>(A2 + (rbase + j) * 16);
            float4 x0 = rr[0], x1 = rr[1], x2 = rr[2], x3 = rr[3];
            a2r[j][0]=x0.x;  a2r[j][1]=x0.y;  a2r[j][2]=x0.z;  a2r[j][3]=x0.w;
            a2r[j][4]=x1.x;  a2r[j][5]=x1.y;  a2r[j][6]=x1.z;  a2r[j][7]=x1.w;
            a2r[j][8]=x2.x;  a2r[j][9]=x2.y;  a2r[j][10]=x2.z; a2r[j][11]=x2.w;
            a2r[j][12]=x3.x; a2r[j][13]=x3.y; a2r[j][14]=x3.z; a2r[j][15]=x3.w;
        }
        float acc[4][16];
        #pragma unroll
        for (int j = 0; j < 4; j++) {
            #pragma unroll
            for (int q = 0; q < 15; q++) acc[j][q] = 0.f;
            acc[j][15] = a2r[j][15];   // M1 row 15 = e15 -> b2 contribution
        }

        #pragma unroll
        for (int k = 0; k < 15; k++) {
            const float4* rr = reinterpret_cast<const float4*>(A1 + k * 16);
            float4 y0 = rr[0], y1 = rr[1], y2 = rr[2], y3 = rr[3];
            float a1r[16] = {y0.x,y0.y,y0.z,y0.w, y1.x,y1.y,y1.z,y1.w,
                             y2.x,y2.y,y2.z,y2.w, y3.x,y3.y,y3.z,y3.w};
            #pragma unroll
            for (int j = 0; j < 4; j++) {
                float c = a2r[j][k];
                #pragma unroll
                for (int q = 0; q < 16; q++)
                    acc[j][q] = fmaf(c, a1r[q], acc[j][q]);
            }
        }
        #pragma unroll
        for (int j = 0; j < 4; j++) {
            float4* o = reinterpret_cast<float4*>(Cp + (rbase + j) * 16);
            o[0] = make_float4(acc[j][0],  acc[j][1],  acc[j][2],  acc[j][3]);
            o[1] = make_float4(acc[j][4],  acc[j][5],  acc[j][6],  acc[j][7]);
            o[2] = make_float4(acc[j][8],  acc[j][9],  acc[j][10], acc[j][11]);
            o[3] = make_float4(acc[j][12], acc[j][13], acc[j][14], acc[j][15]);
        }
    }

    if (half == 1) {
        const float* v1 = sV + (2 * p) * 16;
        const float* v2 = sV + (2 * p + 1) * 16;
        float v2r[16];
        #pragma unroll
        for (int q = 0; q < 16; q++) v2r[q] = v2[q];
        float acc[16];
        #pragma unroll
        for (int q = 0; q < 16; q++) acc[q] = Q * v1[q];
        acc[15] += v2r[15];            // A1 row 15 = e15
        #pragma unroll
        for (int k = 0; k < 15; k++) {
            const float4* rr = reinterpret_cast<const float4*>(A1 + k * 16);
            float4 y0 = rr[0], y1 = rr[1], y2 = rr[2], y3 = rr[3];
            float a1r[16] = {y0.x,y0.y,y0.z,y0.w, y1.x,y1.y,y1.z,y1.w,
                             y2.x,y2.y,y2.z,y2.w, y3.x,y3.y,y3.z,y3.w};
            float c = v2r[k];
            #pragma unroll
            for (int q = 0; q < 16; q++) acc[q] = fmaf(c, a1r[q], acc[q]);
        }
        float4* vo = reinterpret_cast<float4*>(g_V1 + P * 16);
        vo[0] = make_float4(acc[0],  acc[1],  acc[2],  acc[3]);
        vo[1] = make_float4(acc[4],  acc[5],  acc[6],  acc[7]);
        vo[2] = make_float4(acc[8],  acc[9],  acc[10], acc[11]);
        vo[3] = make_float4(acc[12], acc[13], acc[14], acc[15]);
    }
}

// ---------------- generic radix fold: C_out = fold of R consecutive C_in ----
// new row i = sum_{k<15} Mnext[i][k]*Mcur[k][:] + e15 part;
// vnew[i] = Qe*vcur[i] + sum_{k<15} Mcur[k][i]*vnext[k] (+vnext[15] at i=15)
template<int RADIX>
__device__ __forceinline__ void fold_body(const float* Cbase, const float* Vbase,
                                          float* Cout, float* Vout,
                                          float Qe, int slot, int i,
                                          float (&sM)[16][272], float (&sv)[16][16])
{
    {
        const float4* rr = reinterpret_cast<const float4*>(Cbase + i * 16);
        float4 x0 = rr[0], x1 = rr[1], x2 = rr[2], x3 = rr[3];
        float* d = &sM[slot][i * 17];
        d[0]=x0.x;  d[1]=x0.y;  d[2]=x0.z;  d[3]=x0.w;
        d[4]=x1.x;  d[5]=x1.y;  d[6]=x1.z;  d[7]=x1.w;
        d[8]=x2.x;  d[9]=x2.y;  d[10]=x2.z; d[11]=x2.w;
        d[12]=x3.x; d[13]=x3.y; d[14]=x3.z; d[15]=x3.w;
    }
    float vcur = Vbase[i];
    __syncwarp();

    float mrow[16];
    #pragma unroll
    for (int s = 1; s < RADIX; s++) {
        sv[slot][i] = Vbase[s * 16 + i];
        __syncwarp();

        const float4* nr = reinterpret_cast<const float4*>(Cbase + s * 256 + i * 16);
        float4 n0 = nr[0], n1 = nr[1], n2 = nr[2], n3 = nr[3];
        float nc[16] = {n0.x,n0.y,n0.z,n0.w, n1.x,n1.y,n1.z,n1.w,
                        n2.x,n2.y,n2.z,n2.w, n3.x,n3.y,n3.z,n3.w};
        #pragma unroll
        for (int q = 0; q < 16; q++) mrow[q] = 0.f;
        #pragma unroll
        for (int k = 0; k < 15; k++) {
            float c = nc[k];
            const float* mk = &sM[slot][k * 17];
            #pragma unroll
            for (int q = 0; q < 16; q++) mrow[q] = fmaf(c, mk[q], mrow[q]);
        }
        mrow[15] += nc[15];

        float accv = 0.f;
        #pragma unroll
        for (int k = 0; k < 15; k++)
            accv = fmaf(sM[slot][k * 17 + i], sv[slot][k], accv);
        if (i == 15) accv += sv[slot][15];
        vcur = fmaf(Qe, vcur, accv);

        __syncwarp();
        if (s < RADIX - 1) {
            float* d = &sM[slot][i * 17];
            #pragma unroll
            for (int q = 0; q < 16; q++) d[q] = mrow[q];
            __syncwarp();
        }
    }

    float4* og = reinterpret_cast<float4*>(Cout + i * 16);
    og[0] = make_float4(mrow[0],  mrow[1],  mrow[2],  mrow[3]);
    og[1] = make_float4(mrow[4],  mrow[5],  mrow[6],  mrow[7]);
    og[2] = make_float4(mrow[8],  mrow[9],  mrow[10], mrow[11]);
    og[3] = make_float4(mrow[12], mrow[13], mrow[14], mrow[15]);
    Vout[i] = vcur;
}

// compose_oct: radix-4 C1 -> C3 (2 octs per warp)
__global__ void __launch_bounds__(256) k_compose_oct()
{
    __shared__ float sM[16][272];
    __shared__ float sv[16][16];
    const int wig  = threadIdx.x >> 5;
    const int lane = threadIdx.x & 31;
    const int slot = wig * 2 + (lane >> 4);
    const int i    = lane & 15;
    const int gw   = blockIdx.x * 16 + slot;
    const int b    = gw / NF8;
    const int o    = gw - b * NF8;
    float q1 = q_pow80();
    const float Qp = q1 * q1;
    size_t e = (size_t)b * NF2 + 4 * o;
    fold_body<4>(g_C1 + e * 256, g_V1 + e * 16,
                 g_C3 + (size_t)gw * 256, g_V3 + (size_t)gw * 16,
                 Qp, slot, i, sM, sv);
}

// compose4: radix-3 C3 -> C4 (2 units per warp)
__global__ void __launch_bounds__(256) k_compose4()
{
    __shared__ float sM[16][272];
    __shared__ float sv[16][16];
    const int wig  = threadIdx.x >> 5;
    const int lane = threadIdx.x & 31;
    const int slot = wig * 2 + (lane >> 4);
    const int i    = lane & 15;
    const int gw   = blockIdx.x * 16 + slot;
    const int b    = gw / NU;
    const int u    = gw - b * NU;
    float q1 = q_pow80();
    float q2 = q1 * q1, q4 = q2 * q2;
    const float QO = q4 * q4;                 // 0.97^640
    size_t e = (size_t)b * NF8 + 3 * u;
    fold_body<3>(g_C3 + e * 256, g_V3 + e * 16,
                 g_C4 + (size_t)gw * 256, g_V4 + (size_t)gw * 16,
                 QO, slot, i, sM, sv);
}

// compose5: radix-5 C4 -> C5 (2 super-units per warp)
__global__ void __launch_bounds__(256) k_compose5()
{
    __shared__ float sM[16][272];
    __shared__ float sv[16][16];
    const int wig  = threadIdx.x >> 5;
    const int lane = threadIdx.x & 31;
    const int slot = wig * 2 + (lane >> 4);
    const int i    = lane & 15;
    const int gw   = blockIdx.x * 16 + slot;
    const int b    = gw / NSU;
    const int su   = gw - b * NSU;
    float q1 = q_pow80();
    float q2 = q1 * q1, q4 = q2 * q2;
    const float QO = q4 * q4;
    const float QU = QO * QO * QO;            // 0.97^1920
    size_t e = (size_t)b * NU + 5 * su;
    fold_body<5>(g_C4 + e * 256, g_V4 + e * 16,
                 g_C5 + (size_t)gw * 256, g_V5 + (size_t)gw * 16,
                 QU, slot, i, sM, sv);
}

// ---------------- K2: super-unit scan (25 iters, single smem load) ----------
#define CU 84              // float4 per element in smem (16 rows x 5 + 4 v)
#define CG 68              // float4 per element in global (64 + 4)
#define CHG (NSU * CG)     // 1700 float4

__device__ __forceinline__ int k2_dst(int i)
{
    int u = i / CG, r = i - u * CG;
    return u * CU + (r < 64 ? (r >> 2) * 5 + (r & 3) : 80 + (r - 64));
}

__global__ void __launch_bounds__(256, 1) k2_scan()
{
    __shared__ float4 sbuf[NSU * CU];          // 33600 B
    __shared__ __align__(16) float st[16];

    const int b    = blockIdx.x;
    const int tid  = threadIdx.x;
    const int lane = tid & 31;
    const int wid  = tid >> 5;

    float q1 = q_pow80();
    float q2 = q1 * q1, q4 = q2 * q2;
    const float QO = q4 * q4;
    const float QU = QO * QO * QO;
    const float QS = ((QU * QU) * (QU * QU)) * QU;   // 0.97^9600 (~0, exact-enough)

    const float4* srcm = reinterpret_cast<const float4*>(g_C5) + (size_t)b * NSU * 64;
    const float4* srcv = reinterpret_cast<const float4*>(g_V5) + (size_t)b * NSU * 4;
    float* Sp = g_S5 + (size_t)b * NSU * 16 + lane;

    if (tid < 16) st[tid] = (tid == 15) ? 1.f : 0.f;

    for (int i = tid; i < CHG; i += 256) {
        int u = i / CG, r = i - u * CG;
        float4 vl = (r < 64) ? srcm[(size_t)u * 64 + r]
                             : srcv[(size_t)u * 4 + (r - 64)];
        sbuf[k2_dst(i)] = vl;
    }
    __syncthreads();

    if (wid == 0) {
        float sv = 0.f;
        #pragma unroll 5
        for (int d = 0; d < NSU; d++) {
            const float4* rp = (lane < 15) ? (sbuf + d * CU + lane * 5)
                                           : (sbuf + d * CU + 80);
            float4 r0 = rp[0], r1 = rp[1], r2 = rp[2], r3 = rp[3];
            const float4* stv = reinterpret_cast<const float4*>(st);
            float4 s0 = stv[0], s1 = stv[1], s2 = stv[2], s3 = stv[3];

            if (lane < 16) Sp[(size_t)d * 16] = sv;

            float acc0 = fmaf(r0.x, s0.x, fmaf(r0.y, s0.y,
                         fmaf(r0.z, s0.z, r0.w * s0.w)));
            float acc1 = fmaf(r1.x, s1.x, fmaf(r1.y, s1.y,
                         fmaf(r1.z, s1.z, r1.w * s1.w)));
            float acc2 = fmaf(r2.x, s2.x, fmaf(r2.y, s2.y,
                         fmaf(r2.z, s2.z, r2.w * s2.w)));
            float acc3 = fmaf(r3.x, s3.x, fmaf(r3.y, s3.y,
                         fmaf(r3.z, s3.z, r3.w * s3.w)));
            float nsv = (acc0 + acc1) + (acc2 + acc3);
            if (lane == 15) nsv = fmaf(QS, sv, nsv);

            if (lane < NP) st[lane] = nsv;
            __syncwarp(0xffffffffu);
            sv = nsv;
        }
    }
}

// ---------------- shfl matvec -------------------------------------------------
__device__ __forceinline__ float mv_shfl(const float4& r0, const float4& r1,
                                         const float4& r2, const float4& r3,
                                         float sv)
{
    float acc0 = r3.w;
    float acc1 = 0.f, acc2 = 0.f, acc3 = 0.f;
    float bc;
    bc = __shfl_sync(0xffffffffu, sv,  0); acc0 = fmaf(r0.x, bc, acc0);
    bc = __shfl_sync(0xffffffffu, sv,  1); acc1 = fmaf(r0.y, bc, acc1);
    bc = __shfl_sync(0xffffffffu, sv,  2); acc2 = fmaf(r0.z, bc, acc2);
    bc = __shfl_sync(0xffffffffu, sv,  3); acc3 = fmaf(r0.w, bc, acc3);
    bc = __shfl_sync(0xffffffffu, sv,  4); acc0 = fmaf(r1.x, bc, acc0);
    bc = __shfl_sync(0xffffffffu, sv,  5); acc1 = fmaf(r1.y, bc, acc1);
    bc = __shfl_sync(0xffffffffu, sv,  6); acc2 = fmaf(r1.z, bc, acc2);
    bc = __shfl_sync(0xffffffffu, sv,  7); acc3 = fmaf(r1.w, bc, acc3);
    bc = __shfl_sync(0xffffffffu, sv,  8); acc0 = fmaf(r2.x, bc, acc0);
    bc = __shfl_sync(0xffffffffu, sv,  9); acc1 = fmaf(r2.y, bc, acc1);
    bc = __shfl_sync(0xffffffffu, sv, 10); acc2 = fmaf(r2.z, bc, acc2);
    bc = __shfl_sync(0xffffffffu, sv, 11); acc3 = fmaf(r2.w, bc, acc3);
    bc = __shfl_sync(0xffffffffu, sv, 12); acc0 = fmaf(r3.x, bc, acc0);
    bc = __shfl_sync(0xffffffffu, sv, 13); acc1 = fmaf(r3.y, bc, acc1);
    bc = __shfl_sync(0xffffffffu, sv, 14); acc2 = fmaf(r3.z, bc, acc2);
    return (acc0 + acc1) + (acc2 + acc3);
}

// ---------------- k_fill5: super-unit state -> 5 unit states -----------------
__global__ void k_fill5()
{
    int gw = (blockIdx.x * blockDim.x + threadIdx.x) >> 5;
    int lane = threadIdx.x & 31;
    if (gw >= NB * NSU) return;
    int b = gw / NSU;
    int su = gw - b * NSU;

    float q1 = q_pow80();
    float q2 = q1 * q1, q4 = q2 * q2;
    const float QO = q4 * q4;
    const float QU = QO * QO * QO;

    float sv = 0.f;
    const float* s5 = g_S5 + (size_t)gw * 16;
    if (lane < 16) sv = s5[lane];

    size_t e = (size_t)b * NU + 5 * su;
    float* s4 = g_S4 + e * 16;
    if (lane < 16) s4[lane] = sv;

    #pragma unroll
    for (int s = 0; s < 4; s++) {
        const float4* rp = (lane < 15)
            ? reinterpret_cast<const float4*>(g_C4 + (e + s) * 256) + lane * 4
            : reinterpret_cast<const float4*>(g_V4 + (e + s) * 16);
        float4 r0 = rp[0], r1 = rp[1], r2 = rp[2], r3 = rp[3];
        float sn = mv_shfl(r0, r1, r2, r3, sv);
        if (lane == 15) sn = fmaf(QU, sv, sn);
        sv = sn;
        if (lane < 16) s4[(s + 1) * 16 + lane] = sv;
    }
}

// ---------------- k_fill: unit state -> all 12 pair states (11 matvecs) -----
__global__ void k_fill()
{
    int gw = (blockIdx.x * blockDim.x + threadIdx.x) >> 5;
    int lane = threadIdx.x & 31;
    if (gw >= NB * NU) return;
    int b = gw / NU;
    int u = gw - b * NU;

    float q1 = q_pow80();
    const float Qp = q1 * q1;     // per-pair decay

    float sv = 0.f;
    const float* s4 = g_S4 + (size_t)gw * 16;
    if (lane < 16) sv = s4[lane];

    size_t e = (size_t)b * NF2 + 12 * u;
    float* s1 = g_S1 + e * 16;
    if (lane < 16) s1[lane] = sv;

    #pragma unroll
    for (int s = 0; s < 11; s++) {
        const float4* rp = (lane < 15)
            ? reinterpret_cast<const float4*>(g_C1 + (e + s) * 256) + lane * 4
            : reinterpret_cast<const float4*>(g_V1 + (e + s) * 16);
        float4 r0 = rp[0], r1 = rp[1], r2 = rp[2], r3 = rp[3];
        float sn = mv_shfl(r0, r1, r2, r3, sv);
        if (lane == 15) sn = fmaf(Qp, sv, sn);
        sv = sn;
        if (lane < 16) s1[(s + 1) * 16 + lane] = sv;
    }
}

// ---------------- K3: per-pair replay, smem-staged coalesced I/O -------------
#define K3P 64   // pairs per block

__global__ void __launch_bounds__(K3P, 1) k3_apply(const float* __restrict__ excit,
                                                   const float* __restrict__ lpc,
                                                   float* __restrict__ out)
{
    __shared__ float4 sd[K3P * 41];

    const int tid = threadIdx.x;
    const int P0  = blockIdx.x * K3P;

    for (int e = tid; e < K3P * 40; e += K3P) {
        int j = e / 40, o = e - j * 40;
        int gp = P0 + j;
        int b = gp / NF2, g = gp - b * NF2;
        const float4* src = reinterpret_cast<const float4*>(
            excit + (size_t)b * NL + (size_t)g * 2 * NFS);
        sd[j * 41 + o] = src[o];
    }
    __syncthreads();

    {
        int gp = P0 + tid;
        int b = gp / NF2, g = gp - b * NF2;

        float aA[16], aB[16];
        const float* apA = lpc + ((size_t)b * NF + 2 * g) * 16;
        #pragma unroll
        for (int k = 1; k < 16; k++) aA[k] = apA[k];
        #pragma unroll
        for (int k = 1; k < 16; k++) aB[k] = apA[16 + k];

        const float* sp = g_S1 + (size_t)gp * 16;
        float hist[NP];
        #pragma unroll
        for (int k = 0; k < NP; k++) hist[k] = sp[k];
        float w = sp[15];

        float4* my = &sd[tid * 41];
        #pragma unroll
        for (int m4 = 0; m4 < 40; m4++) {
            float4 e4 = my[m4];
            float ev[4] = {e4.x, e4.y, e4.z, e4.w};
            float ov[4];
            const bool first = (m4 < 20);
            #pragma unroll
            for (int q = 0; q < 4; q++) {
                float acc = first ? ar_step(aA, hist, ev[q])
                                  : ar_step(aB, hist, ev[q]);
                #pragma unroll
                for (int k = NP - 1; k >= 1; k--) hist[k] = hist[k - 1];
                hist[0] = acc;
                w = fmaf(EMPH, w, acc);
                ov[q] = w;
            }
            my[m4] = make_float4(ov[0], ov[1], ov[2], ov[3]);
        }
    }
    __syncthreads();

    for (int e = tid; e < K3P * 40; e += K3P) {
        int j = e / 40, o = e - j * 40;
        int gp = P0 + j;
        int b = gp / NF2, g = gp - b * NF2;
        float4* dst = reinterpret_cast<float4*>(
            out + (size_t)b * NL + (size_t)g * 2 * NFS);
        dst[o] = sd[j * 41 + o];
    }
}

// ---------------- launch -----------------------------------------------------
extern "C" void kernel_launch(void* const* d_in, const int* in_sizes, int n_in,
                              void* d_out, int out_size)
{
    const float* excit = (const float*)d_in[0];
    const float* lpc   = (const float*)d_in[1];
    if (n_in >= 2 && in_sizes[0] == NB * NF * 16 && in_sizes[1] == NB * NL) {
        excit = (const float*)d_in[1];
        lpc   = (const float*)d_in[0];
    }
    float* out = (float*)d_out;

    kA_fused<<<NB * NF / 32, 32>>>(excit, lpc);
    k_compose_oct<<<NB * NF8 / 16, 256>>>();
    k_compose4<<<(NB * NU + 15) / 16, 256>>>();
    k_compose5<<<NB * NSU / 16, 256>>>();
    k2_scan<<<NB, 256>>>();
    k_fill5<<<NB * NSU * 32 / 256, 256>>>();
    k_fill<<<NB * NU * 32 / 256, 256>>>();
    k3_apply<<<NB * NF2 / K3P, K3P>>>(excit, lpc, out);
}